// round 2
// baseline (speedup 1.0000x reference)
#include <cuda_runtime.h>

// Problem constants (B=64, C=512, H=W=28, G=8)
#define HWN  784      // H*W
#define HW4  196      // HW / 4 (float4 elements per channel row)
#define CPG  64       // channels per group
#define NBG  512      // B*G blocks
#define EPS  1e-5f

__global__ __launch_bounds__(256)
void simam_group_gate_kernel(const float* __restrict__ x,
                             const float* __restrict__ weight,
                             const float* __restrict__ bias,
                             float* __restrict__ out)
{
    __shared__ float  s_means[CPG];
    __shared__ float4 s_gate4[HW4];
    __shared__ float  s_red[18];

    const int bg = blockIdx.x;             // bg = b*8 + g; tile is contiguous
    const int g  = bg & 7;
    const float* xt = x   + (size_t)bg * (CPG * HWN);
    float*       ot = out + (size_t)bg * (CPG * HWN);

    const int tid  = threadIdx.x;
    const int w    = tid >> 5;
    const int lane = tid & 31;

    // ---------------- Pass A: per-channel spatial means (DRAM read, fills L2)
    for (int c = w; c < CPG; c += 8) {
        const float4* row = (const float4*)(xt + c * HWN);
        float s = 0.f;
        #pragma unroll
        for (int j = lane; j < HW4; j += 32) {
            float4 v = row[j];
            s += (v.x + v.y) + (v.z + v.w);
        }
        #pragma unroll
        for (int o = 16; o; o >>= 1) s += __shfl_xor_sync(0xffffffffu, s, o);
        if (lane == 0) s_means[c] = s * (1.0f / HWN);
    }
    __syncthreads();

    // ---------------- Pass B: s[hw] = sum_c m[c]*x[c,hw]  (L2 re-read)
    float4 acc = make_float4(0.f, 0.f, 0.f, 0.f);
    float lsum = 0.f, lsq = 0.f;
    if (tid < HW4) {
        #pragma unroll 8
        for (int c = 0; c < CPG; c++) {
            const float  m = s_means[c];
            const float4 v = ((const float4*)(xt + c * HWN))[tid];
            acc.x += m * v.x;
            acc.y += m * v.y;
            acc.z += m * v.z;
            acc.w += m * v.w;
        }
        lsum = (acc.x + acc.y) + (acc.z + acc.w);
        lsq  = acc.x * acc.x + acc.y * acc.y + acc.z * acc.z + acc.w * acc.w;
    }
    // block reduce sum and sumsq over all 256 threads (inactive contribute 0)
    #pragma unroll
    for (int o = 16; o; o >>= 1) {
        lsum += __shfl_xor_sync(0xffffffffu, lsum, o);
        lsq  += __shfl_xor_sync(0xffffffffu, lsq,  o);
    }
    if (lane == 0) { s_red[w] = lsum; s_red[8 + w] = lsq; }
    __syncthreads();
    if (tid == 0) {
        float ts = 0.f, tq = 0.f;
        #pragma unroll
        for (int i = 0; i < 8; i++) { ts += s_red[i]; tq += s_red[8 + i]; }
        const float mu  = ts * (1.0f / HWN);
        const float var = tq * (1.0f / HWN) - mu * mu;
        s_red[16] = mu;
        s_red[17] = rsqrtf(var + EPS);
    }
    __syncthreads();

    {
        const float mu = s_red[16];
        const float rs = s_red[17];
        const float wg = weight[g];
        const float bb = bias[g];
        if (tid < HW4) {
            float4 gt;
            gt.x = 1.0f / (1.0f + __expf(-((acc.x - mu) * rs * wg + bb)));
            gt.y = 1.0f / (1.0f + __expf(-((acc.y - mu) * rs * wg + bb)));
            gt.z = 1.0f / (1.0f + __expf(-((acc.z - mu) * rs * wg + bb)));
            gt.w = 1.0f / (1.0f + __expf(-((acc.w - mu) * rs * wg + bb)));
            s_gate4[tid] = gt;
        }
    }
    __syncthreads();

    // ---------------- Pass C: out = x * gate (L2 re-read + DRAM write)
    for (int c = w; c < CPG; c += 8) {
        const float4* row  = (const float4*)(xt + c * HWN);
        float4*       orow = (float4*)(ot + c * HWN);
        #pragma unroll
        for (int j = lane; j < HW4; j += 32) {
            float4 v  = row[j];
            float4 gt = s_gate4[j];
            v.x *= gt.x; v.y *= gt.y; v.z *= gt.z; v.w *= gt.w;
            orow[j] = v;
        }
    }
}

extern "C" void kernel_launch(void* const* d_in, const int* in_sizes, int n_in,
                              void* d_out, int out_size)
{
    const float* x  = (const float*)d_in[0];
    const float* wt = (const float*)d_in[1];
    const float* bs = (const float*)d_in[2];
    float* out = (float*)d_out;
    simam_group_gate_kernel<<<NBG, 256>>>(x, wt, bs, out);
}

// round 4
// speedup vs baseline: 1.0422x; 1.0422x over previous
#include <cuda_runtime.h>

// Problem constants (B=64, C=512, H=W=28, G=8)
#define HWN  784      // H*W
#define HW4  196      // HW / 4 (float4 per channel row)
#define CPG  64       // channels per group
#define NBG  512      // B*G tiles
#define EPS  1e-5f
#define K7   7        // ceil(HW4/32) float4 per lane

// dynamic smem layout (floats):
//   [0, CPG*HWN)              x tile (64 x 784)
//   [CPG*HWN, +HWN)           s array (784 floats = 196 float4)
//   [.., +32)                 reduction scratch
#define SMEM_FLOATS (CPG * HWN + HWN + 32)
#define SMEM_BYTES  (SMEM_FLOATS * 4)

__global__ __launch_bounds__(256, 1)
void simam_smem_kernel(const float* __restrict__ x,
                       const float* __restrict__ weight,
                       const float* __restrict__ bias,
                       float* __restrict__ out)
{
    extern __shared__ float smem[];
    float*  sx    = smem;                       // x tile
    float4* s_s4  = (float4*)(smem + CPG * HWN); // partial/final s (196 float4)
    float*  s_red = smem + CPG * HWN + HWN;      // 32 floats scratch

    const int bg = blockIdx.x;
    const int g  = bg & 7;
    const float* xt = x   + (size_t)bg * (CPG * HWN);
    float*       ot = out + (size_t)bg * (CPG * HWN);

    const int tid  = threadIdx.x;
    const int w    = tid >> 5;
    const int lane = tid & 31;

    // zero the s accumulator
    if (tid < HW4) s_s4[tid] = make_float4(0.f, 0.f, 0.f, 0.f);
    __syncthreads();

    // ---- fused: DRAM load -> channel mean -> stash in smem -> accumulate m*x into s
    float4 acc[K7];
    #pragma unroll
    for (int k = 0; k < K7; k++) acc[k] = make_float4(0.f, 0.f, 0.f, 0.f);

    for (int c = w; c < CPG; c += 8) {
        const float4* row = (const float4*)(xt + c * HWN);
        float4 v[K7];
        float  csum = 0.f;
        #pragma unroll
        for (int k = 0; k < K7; k++) {
            const int j = lane + 32 * k;
            if (j < HW4) {
                v[k] = row[j];
                csum += (v[k].x + v[k].y) + (v[k].z + v[k].w);
            }
        }
        #pragma unroll
        for (int o = 16; o; o >>= 1) csum += __shfl_xor_sync(0xffffffffu, csum, o);
        const float m = csum * (1.0f / HWN);

        float4* srow = (float4*)(sx + c * HWN);
        #pragma unroll
        for (int k = 0; k < K7; k++) {
            const int j = lane + 32 * k;
            if (j < HW4) {
                srow[j] = v[k];
                acc[k].x += m * v[k].x;
                acc[k].y += m * v[k].y;
                acc[k].z += m * v[k].z;
                acc[k].w += m * v[k].w;
            }
        }
    }

    // merge per-warp partial s via shared atomics (spread addresses, 8-way max)
    #pragma unroll
    for (int k = 0; k < K7; k++) {
        const int j = lane + 32 * k;
        if (j < HW4) {
            float* p = (float*)&s_s4[j];
            atomicAdd(p + 0, acc[k].x);
            atomicAdd(p + 1, acc[k].y);
            atomicAdd(p + 2, acc[k].z);
            atomicAdd(p + 3, acc[k].w);
        }
    }
    __syncthreads();

    // ---- stats over s (784 elements)
    float lsum = 0.f, lsq = 0.f;
    if (tid < HW4) {
        const float4 sv = s_s4[tid];
        lsum = (sv.x + sv.y) + (sv.z + sv.w);
        lsq  = sv.x * sv.x + sv.y * sv.y + sv.z * sv.z + sv.w * sv.w;
    }
    #pragma unroll
    for (int o = 16; o; o >>= 1) {
        lsum += __shfl_xor_sync(0xffffffffu, lsum, o);
        lsq  += __shfl_xor_sync(0xffffffffu, lsq,  o);
    }
    if (lane == 0) { s_red[w] = lsum; s_red[8 + w] = lsq; }
    __syncthreads();
    if (tid == 0) {
        float ts = 0.f, tq = 0.f;
        #pragma unroll
        for (int i = 0; i < 8; i++) { ts += s_red[i]; tq += s_red[8 + i]; }
        const float mu  = ts * (1.0f / HWN);
        const float var = tq * (1.0f / HWN) - mu * mu;
        s_red[16] = mu;
        s_red[17] = rsqrtf(var + EPS);
    }
    __syncthreads();

    // ---- gate, written in place over s
    {
        const float mu = s_red[16];
        const float rs = s_red[17];
        const float wg = weight[g];
        const float bb = bias[g];
        if (tid < HW4) {
            float4 sv = s_s4[tid];
            float4 gt;
            gt.x = 1.0f / (1.0f + __expf(-((sv.x - mu) * rs * wg + bb)));
            gt.y = 1.0f / (1.0f + __expf(-((sv.y - mu) * rs * wg + bb)));
            gt.z = 1.0f / (1.0f + __expf(-((sv.z - mu) * rs * wg + bb)));
            gt.w = 1.0f / (1.0f + __expf(-((sv.w - mu) * rs * wg + bb)));
            s_s4[tid] = gt;
        }
    }
    __syncthreads();

    // ---- pass C: out = x * gate, straight from smem (single DRAM write sweep)
    float4 gt[K7];
    #pragma unroll
    for (int k = 0; k < K7; k++) {
        const int j = lane + 32 * k;
        gt[k] = (j < HW4) ? s_s4[j] : make_float4(0.f, 0.f, 0.f, 0.f);
    }
    for (int c = w; c < CPG; c += 8) {
        const float4* srow = (const float4*)(sx + c * HWN);
        float4*       orow = (float4*)(ot + c * HWN);
        #pragma unroll
        for (int k = 0; k < K7; k++) {
            const int j = lane + 32 * k;
            if (j < HW4) {
                float4 v = srow[j];
                v.x *= gt[k].x; v.y *= gt[k].y; v.z *= gt[k].z; v.w *= gt[k].w;
                orow[j] = v;
            }
        }
    }
}

extern "C" void kernel_launch(void* const* d_in, const int* in_sizes, int n_in,
                              void* d_out, int out_size)
{
    const float* x  = (const float*)d_in[0];
    const float* wt = (const float*)d_in[1];
    const float* bs = (const float*)d_in[2];
    float* out = (float*)d_out;

    cudaFuncSetAttribute(simam_smem_kernel,
                         cudaFuncAttributeMaxDynamicSharedMemorySize, SMEM_BYTES);
    simam_smem_kernel<<<NBG, 256, SMEM_BYTES>>>(x, wt, bs, out);
}

// round 5
// speedup vs baseline: 1.2879x; 1.2357x over previous
#include <cuda_runtime.h>
#include <cstdint>

// Problem constants (B=64, C=512, H=W=28, G=8)
#define HWN   784       // H*W
#define HW4   196       // HW/4 (float4 per channel row)
#define CPG   64        // channels per group
#define NBG   512       // B*G tiles
#define EPS   1e-5f
#define NTHR  512       // 16 warps
#define NW    16
#define K7    7         // float4 per lane across a row (196/32 -> 7 w/ guard)

#define TILE_BYTES   (CPG * HWN * 4)   // 200704
#define CHUNK_BYTES  (TILE_BYTES / 8)  // 25088

// dynamic smem layout (floats):
//   [0, CPG*HWN)      x tile (50176 floats)
//   + HWN             s / gate array (784 floats, viewed as 196 float4)
//   + CPG             channel means
//   + 40              reduction scratch (32 partials + mu/rsig)
//   + mbarrier (16B aligned at end)
#define SMEM_X_FLOATS (CPG * HWN)
#define SMEM_FLOATS   (SMEM_X_FLOATS + HWN + CPG + 40 + 8)
#define SMEM_BYTES    (SMEM_FLOATS * 4)

__device__ __forceinline__ uint32_t smem_u32(const void* p) {
    uint32_t a;
    asm("{ .reg .u64 t; cvta.to.shared.u64 t, %1; cvt.u32.u64 %0, t; }"
        : "=r"(a) : "l"(p));
    return a;
}

__global__ __launch_bounds__(NTHR, 1)
void simam_tma_kernel(const float* __restrict__ x,
                      const float* __restrict__ weight,
                      const float* __restrict__ bias,
                      float* __restrict__ out)
{
    extern __shared__ float smem[];
    float*  sx      = smem;
    float4* s_s4    = (float4*)(smem + SMEM_X_FLOATS);           // 196 float4
    float*  s_means = smem + SMEM_X_FLOATS + HWN;                // 64
    float*  s_red   = s_means + CPG;                             // 40
    // mbarrier: 8-byte aligned slot past scratch
    uint64_t* mbar_p = (uint64_t*)(s_red + 40);
    const uint32_t mbar = smem_u32(mbar_p);

    const int bg = blockIdx.x;
    const int g  = bg & 7;
    const float* xt = x   + (size_t)bg * (CPG * HWN);
    float*       ot = out + (size_t)bg * (CPG * HWN);

    const int tid  = threadIdx.x;
    const int w    = tid >> 5;
    const int lane = tid & 31;

    // ---------------- TMA bulk load of the whole contiguous tile ----------------
    if (tid == 0) {
        asm volatile("mbarrier.init.shared::cta.b64 [%0], 1;" :: "r"(mbar) : "memory");
    }
    __syncthreads();
    if (tid == 0) {
        asm volatile("mbarrier.arrive.expect_tx.shared::cta.b64 _, [%0], %1;"
                     :: "r"(mbar), "r"((uint32_t)TILE_BYTES) : "memory");
        const uint32_t dst0 = smem_u32(sx);
        #pragma unroll
        for (int i = 0; i < 8; i++) {
            asm volatile(
                "cp.async.bulk.shared::cluster.global.mbarrier::complete_tx::bytes "
                "[%0], [%1], %2, [%3];"
                :: "r"(dst0 + i * CHUNK_BYTES),
                   "l"((const char*)xt + i * CHUNK_BYTES),
                   "r"((uint32_t)CHUNK_BYTES),
                   "r"(mbar)
                : "memory");
        }
    }
    // all threads wait for tile arrival (phase parity 0)
    {
        asm volatile(
            "{\n\t"
            ".reg .pred P;\n\t"
            "WL_%=: mbarrier.try_wait.parity.acquire.cta.shared::cta.b64 P, [%0], 0, 0x989680;\n\t"
            "@P bra WD_%=;\n\t"
            "bra WL_%=;\n\t"
            "WD_%=:\n\t"
            "}" :: "r"(mbar) : "memory");
    }

    // ---------------- sweep 1a: per-channel means (16 warps x 4 channels) -------
    for (int c = w; c < CPG; c += NW) {
        const float4* row = (const float4*)(sx + c * HWN);
        float csum = 0.f;
        #pragma unroll
        for (int k = 0; k < K7; k++) {
            const int j = lane + 32 * k;
            if (j < HW4) {
                float4 v = row[j];
                csum += (v.x + v.y) + (v.z + v.w);
            }
        }
        #pragma unroll
        for (int o = 16; o; o >>= 1) csum += __shfl_xor_sync(0xffffffffu, csum, o);
        if (lane == 0) s_means[c] = csum * (1.0f / HWN);
    }
    __syncthreads();

    // ---------------- sweep 1b: s[hw] = sum_c m[c] * x[c,hw] (no atomics) -------
    float4 acc = make_float4(0.f, 0.f, 0.f, 0.f);
    float lsum = 0.f, lsq = 0.f;
    if (tid < HW4) {
        const float4* col = (const float4*)sx + tid;   // stride HWN/4 between channels
        #pragma unroll 8
        for (int c = 0; c < CPG; c++) {
            const float  m = s_means[c];
            const float4 v = col[c * (HWN / 4)];
            acc.x += m * v.x;
            acc.y += m * v.y;
            acc.z += m * v.z;
            acc.w += m * v.w;
        }
        lsum = (acc.x + acc.y) + (acc.z + acc.w);
        lsq  = acc.x * acc.x + acc.y * acc.y + acc.z * acc.z + acc.w * acc.w;
    }
    #pragma unroll
    for (int o = 16; o; o >>= 1) {
        lsum += __shfl_xor_sync(0xffffffffu, lsum, o);
        lsq  += __shfl_xor_sync(0xffffffffu, lsq,  o);
    }
    if (lane == 0) { s_red[w] = lsum; s_red[NW + w] = lsq; }
    __syncthreads();
    if (tid == 0) {
        float ts = 0.f, tq = 0.f;
        #pragma unroll
        for (int i = 0; i < NW; i++) { ts += s_red[i]; tq += s_red[NW + i]; }
        const float mu  = ts * (1.0f / HWN);
        const float var = tq * (1.0f / HWN) - mu * mu;
        s_red[32] = mu;
        s_red[33] = rsqrtf(var + EPS);
    }
    __syncthreads();

    // ---------------- gate (written into s buffer) ------------------------------
    {
        const float mu = s_red[32];
        const float rs = s_red[33];
        const float wg = weight[g];
        const float bb = bias[g];
        if (tid < HW4) {
            float4 gt;
            gt.x = 1.0f / (1.0f + __expf(-((acc.x - mu) * rs * wg + bb)));
            gt.y = 1.0f / (1.0f + __expf(-((acc.y - mu) * rs * wg + bb)));
            gt.z = 1.0f / (1.0f + __expf(-((acc.z - mu) * rs * wg + bb)));
            gt.w = 1.0f / (1.0f + __expf(-((acc.w - mu) * rs * wg + bb)));
            s_s4[tid] = gt;
        }
    }
    __syncthreads();

    // ---------------- multiply + store (STG fire-and-forget) --------------------
    float4 gt[K7];
    #pragma unroll
    for (int k = 0; k < K7; k++) {
        const int j = lane + 32 * k;
        gt[k] = (j < HW4) ? s_s4[j] : make_float4(0.f, 0.f, 0.f, 0.f);
    }
    for (int c = w; c < CPG; c += NW) {
        const float4* srow = (const float4*)(sx + c * HWN);
        float4*       orow = (float4*)(ot + c * HWN);
        #pragma unroll
        for (int k = 0; k < K7; k++) {
            const int j = lane + 32 * k;
            if (j < HW4) {
                float4 v = srow[j];
                v.x *= gt[k].x; v.y *= gt[k].y; v.z *= gt[k].z; v.w *= gt[k].w;
                orow[j] = v;
            }
        }
    }
}

extern "C" void kernel_launch(void* const* d_in, const int* in_sizes, int n_in,
                              void* d_out, int out_size)
{
    const float* x  = (const float*)d_in[0];
    const float* wt = (const float*)d_in[1];
    const float* bs = (const float*)d_in[2];
    float* out = (float*)d_out;

    cudaFuncSetAttribute(simam_tma_kernel,
                         cudaFuncAttributeMaxDynamicSharedMemorySize, SMEM_BYTES);
    simam_tma_kernel<<<NBG, NTHR, SMEM_BYTES>>>(x, wt, bs, out);
}